// round 14
// baseline (speedup 1.0000x reference)
#include <cuda_runtime.h>

// PCEN: smooth[t] = 0.975*smooth[t-1] + 0.025*x[t], smooth[0]=x[0]
//       out = (x / (smooth+1e-6)^0.98 + 2)^0.5 - 2^0.5
//
// Exact warp-cooperative scan, TWO independent rows per warp. Per step
// the bodies of row A and row B interleave: two independent Kogge-Stone
// shuffle chains, two MUFU chains, two loads in flight -> 2x ILP on the
// critical path that R10/R13 exposed (nothing saturated, issue 60%).
// Everything else identical to the 49.2us kernel: lane-contiguous float4
// I/O (512B/warp request per row), 1-FMA serial carry per step per row,
// streaming stores, no SMEM, no barriers, exact.

namespace {

constexpr int T_LEN = 4096;
constexpr int WPB   = 8;              // warps per block
constexpr int STEP  = 128;            // elements per row per warp-step
constexpr int NSTEP = T_LEN / STEP;   // 32

constexpr float A1 = 0.975f;
constexpr float S  = 0.025f;
constexpr float C1  = A1 * A1 * A1 * A1;   // 0.975^4
constexpr float C2  = C1 * C1;             // ^8
constexpr float C4  = C2 * C2;             // ^16
constexpr float C8  = C4 * C4;             // ^32
constexpr float C16 = C8 * C8;             // ^64
constexpr float C32 = C16 * C16;           // ^128

__device__ __forceinline__ float pcen_pt(float xv, float sm) {
    float l = __log2f(sm + 1e-6f);                // MUFU.LG2
    float g = exp2f(-0.98f * l);                  // MUFU.EX2
    float v = fmaf(xv, g, 2.0f);
    return rsqrtf(v) * v - 1.41421356237309515f;  // MUFU.RSQ; v >= 2
}

__global__ __launch_bounds__(WPB * 32)
void pcen_kernel(const float* __restrict__ x, float* __restrict__ out,
                 int npairs) {
    const int lane = threadIdx.x & 31;
    const int pair = blockIdx.x * WPB + (threadIdx.x >> 5);
    if (pair >= npairs) return;

    const size_t rowA = (size_t)(2 * pair) * T_LEN;
    const float4* __restrict__ xa = reinterpret_cast<const float4*>(x + rowA) + lane;
    const float4* __restrict__ xb = xa + T_LEN / 4;
    float4* __restrict__ oa = reinterpret_cast<float4*>(out + rowA) + lane;
    float4* __restrict__ ob = oa + T_LEN / 4;

    // Al = C1^lane via binary expansion (compile-time constants)
    float Al = 1.0f;
    if (lane & 1)  Al *= C1;
    if (lane & 2)  Al *= C2;
    if (lane & 4)  Al *= C4;
    if (lane & 8)  Al *= C8;
    if (lane & 16) Al *= C16;

    const unsigned FULL = 0xffffffffu;

    float4 va = xa[0];
    float4 vb = xb[0];
    float carryA = __shfl_sync(FULL, va.x, 0);  // fixed point: smooth[0]=x[0]
    float carryB = __shfl_sync(FULL, vb.x, 0);

    #pragma unroll 4
    for (int k = 0; k < NSTEP; ++k) {
        float4 na = va, nb = vb;
        if (k + 1 < NSTEP) {
            na = xa[(k + 1) * (STEP / 4)];
            nb = xb[(k + 1) * (STEP / 4)];
        }

        // lane-local affine offsets (independent chains)
        float ba = fmaf(A1, va.x, va.y);
        float bb = fmaf(A1, vb.x, vb.y);
        ba = fmaf(A1, ba, va.z);   bb = fmaf(A1, bb, vb.z);
        ba = fmaf(A1, ba, va.w);   bb = fmaf(A1, bb, vb.w);
        ba *= S;                   bb *= S;

        // two interleaved Kogge-Stone scans
        float pa = ba, pb = bb, ta, tb;
        ta = __shfl_up_sync(FULL, pa, 1);
        tb = __shfl_up_sync(FULL, pb, 1);
        if (lane >= 1)  { pa = fmaf(C1, ta, pa);  pb = fmaf(C1, tb, pb); }
        ta = __shfl_up_sync(FULL, pa, 2);
        tb = __shfl_up_sync(FULL, pb, 2);
        if (lane >= 2)  { pa = fmaf(C2, ta, pa);  pb = fmaf(C2, tb, pb); }
        ta = __shfl_up_sync(FULL, pa, 4);
        tb = __shfl_up_sync(FULL, pb, 4);
        if (lane >= 4)  { pa = fmaf(C4, ta, pa);  pb = fmaf(C4, tb, pb); }
        ta = __shfl_up_sync(FULL, pa, 8);
        tb = __shfl_up_sync(FULL, pb, 8);
        if (lane >= 8)  { pa = fmaf(C8, ta, pa);  pb = fmaf(C8, tb, pb); }
        ta = __shfl_up_sync(FULL, pa, 16);
        tb = __shfl_up_sync(FULL, pb, 16);
        if (lane >= 16) { pa = fmaf(C16, ta, pa); pb = fmaf(C16, tb, pb); }

        float ppA = __shfl_up_sync(FULL, pa, 1);
        float ppB = __shfl_up_sync(FULL, pb, 1);
        if (lane == 0) { ppA = 0.0f; ppB = 0.0f; }
        float p31A = __shfl_sync(FULL, pa, 31);
        float p31B = __shfl_sync(FULL, pb, 31);

        float sA = fmaf(Al, carryA, ppA);
        float sB = fmaf(Al, carryB, ppB);
        carryA = fmaf(C32, carryA, p31A);     // 1 FMA serial chain per row
        carryB = fmaf(C32, carryB, p31B);

        // reconstruct + transform + store, row A then row B (independent)
        {
            float s0 = fmaf(A1, sA, S * va.x);
            float s1 = fmaf(A1, s0, S * va.y);
            float s2 = fmaf(A1, s1, S * va.z);
            float s3 = fmaf(A1, s2, S * va.w);
            float4 o;
            o.x = pcen_pt(va.x, s0);
            o.y = pcen_pt(va.y, s1);
            o.z = pcen_pt(va.z, s2);
            o.w = pcen_pt(va.w, s3);
            __stcs(&oa[k * (STEP / 4)], o);
        }
        {
            float s0 = fmaf(A1, sB, S * vb.x);
            float s1 = fmaf(A1, s0, S * vb.y);
            float s2 = fmaf(A1, s1, S * vb.z);
            float s3 = fmaf(A1, s2, S * vb.w);
            float4 o;
            o.x = pcen_pt(vb.x, s0);
            o.y = pcen_pt(vb.y, s1);
            o.z = pcen_pt(vb.z, s2);
            o.w = pcen_pt(vb.w, s3);
            __stcs(&ob[k * (STEP / 4)], o);
        }

        va = na; vb = nb;
    }
}

}  // namespace

extern "C" void kernel_launch(void* const* d_in, const int* in_sizes, int n_in,
                              void* d_out, int out_size) {
    const float* x = (const float*)d_in[0];
    float* out = (float*)d_out;
    int nrows = in_sizes[0] / T_LEN;            // 8192
    int npairs = nrows / 2;                     // 4096 warps, 2 rows each
    int blocks = (npairs + WPB - 1) / WPB;      // 512 blocks
    pcen_kernel<<<blocks, WPB * 32>>>(x, out, npairs);
}

// round 15
// speedup vs baseline: 1.0975x; 1.0975x over previous
#include <cuda_runtime.h>

// PCEN: smooth[t] = 0.975*smooth[t-1] + 0.025*x[t], smooth[0]=x[0]
//       out = (x / (smooth+1e-6)^0.98 + 2)^0.5 - 2^0.5
//
// FINAL: exact warp-cooperative scan. One warp owns one full row (T=4096),
// 32 steps of 128 elements, lane-contiguous float4 I/O (512B/warp request).
// Per step: lane-local Horner fold (4 elems -> affine offset, decay
// 0.975^4), 5-round Kogge-Stone shuffle scan, 4-smooth reconstruct, PCEN
// transform, streaming store. Cross-step serial chain is ONE FMA
// (carry' = 0.975^128*carry + p31). No SMEM, no barriers, no lookback
// approximation. 8192 warps = full-chip single wave.
//
// This sits at the memory floor: 268 MB moved in ~42.5us (ncu) = 6.3 TB/s
// = ~79% of HBM spec, the practical ceiling for a balanced r/w stream mix.
// Probes of every other axis (deeper prefetch, 2-row ILP, chunked
// occupancy, wider bursts, scan-frequency halving) were neutral or worse.

namespace {

constexpr int T_LEN = 4096;
constexpr int WPB   = 8;              // warps per block
constexpr int STEP  = 128;            // elements per warp-step
constexpr int NSTEP = T_LEN / STEP;   // 32

constexpr float A1 = 0.975f;
constexpr float S  = 0.025f;
constexpr float C1  = A1 * A1 * A1 * A1;   // 0.975^4
constexpr float C2  = C1 * C1;             // ^8
constexpr float C4  = C2 * C2;             // ^16
constexpr float C8  = C4 * C4;             // ^32
constexpr float C16 = C8 * C8;             // ^64
constexpr float C32 = C16 * C16;           // ^128

__device__ __forceinline__ float pcen_pt(float xv, float sm) {
    float l = __log2f(sm + 1e-6f);                // MUFU.LG2
    float g = exp2f(-0.98f * l);                  // MUFU.EX2
    float v = fmaf(xv, g, 2.0f);
    return rsqrtf(v) * v - 1.41421356237309515f;  // MUFU.RSQ; v >= 2
}

__global__ __launch_bounds__(WPB * 32)
void pcen_kernel(const float* __restrict__ x, float* __restrict__ out) {
    const int lane = threadIdx.x & 31;
    const int row  = blockIdx.x * WPB + (threadIdx.x >> 5);  // grid exact

    const float4* __restrict__ xr =
        reinterpret_cast<const float4*>(x + (size_t)row * T_LEN) + lane;
    float4* __restrict__ orow =
        reinterpret_cast<float4*>(out + (size_t)row * T_LEN) + lane;

    // Al = C1^lane via binary expansion (compile-time constants)
    float Al = 1.0f;
    if (lane & 1)  Al *= C1;
    if (lane & 2)  Al *= C2;
    if (lane & 4)  Al *= C4;
    if (lane & 8)  Al *= C8;
    if (lane & 16) Al *= C16;

    const unsigned FULL = 0xffffffffu;

    float4 v = xr[0];
    float carry = __shfl_sync(FULL, v.x, 0);   // fixed point: smooth[0] = x[0]

    #pragma unroll 4
    for (int k = 0; k < NSTEP; ++k) {
        float4 vn = v;
        if (k + 1 < NSTEP) vn = xr[(k + 1) * (STEP / 4)];

        // lane-local affine offset: b = S*(A1^3 x0 + A1^2 x1 + A1 x2 + x3)
        float b = fmaf(A1, v.x, v.y);
        b = fmaf(A1, b, v.z);
        b = fmaf(A1, b, v.w);
        b *= S;

        // Kogge-Stone inclusive scan with decay C1 per lane-hop
        float p = b, tt;
        tt = __shfl_up_sync(FULL, p, 1);  if (lane >= 1)  p = fmaf(C1, tt, p);
        tt = __shfl_up_sync(FULL, p, 2);  if (lane >= 2)  p = fmaf(C2, tt, p);
        tt = __shfl_up_sync(FULL, p, 4);  if (lane >= 4)  p = fmaf(C4, tt, p);
        tt = __shfl_up_sync(FULL, p, 8);  if (lane >= 8)  p = fmaf(C8, tt, p);
        tt = __shfl_up_sync(FULL, p, 16); if (lane >= 16) p = fmaf(C16, tt, p);

        float pprev = __shfl_up_sync(FULL, p, 1);
        if (lane == 0) pprev = 0.0f;
        float p31 = __shfl_sync(FULL, p, 31);

        float s_in = fmaf(Al, carry, pprev);   // state entering this lane
        carry = fmaf(C32, carry, p31);         // serial chain: ONE FMA per step

        float sm0 = fmaf(A1, s_in, S * v.x);
        float sm1 = fmaf(A1, sm0,  S * v.y);
        float sm2 = fmaf(A1, sm1,  S * v.z);
        float sm3 = fmaf(A1, sm2,  S * v.w);
        float4 o;
        o.x = pcen_pt(v.x, sm0);
        o.y = pcen_pt(v.y, sm1);
        o.z = pcen_pt(v.z, sm2);
        o.w = pcen_pt(v.w, sm3);
        __stcs(&orow[k * (STEP / 4)], o);

        v = vn;
    }
}

}  // namespace

extern "C" void kernel_launch(void* const* d_in, const int* in_sizes, int n_in,
                              void* d_out, int out_size) {
    const float* x = (const float*)d_in[0];
    float* out = (float*)d_out;
    int nrows = in_sizes[0] / T_LEN;            // 8192 warps, one per row
    int blocks = nrows / WPB;                   // 1024 blocks (exact)
    pcen_kernel<<<blocks, WPB * 32>>>(x, out);
}